// round 2
// baseline (speedup 1.0000x reference)
#include <cuda_runtime.h>
#include <math.h>

#define NB   4
#define NP   1024
#define DD   256
#define HH   64
#define WW   64
#define HWT  4096
#define HEADS 8
#define DH   32

// ---------------------------------------------------------------------------
// Scratch: one __device__ array, partitioned on the host side.
//   lf  : NB*NP*DD    (1M floats)
//   gf  : NB*HWT*DD   (4M)
//   q   : NB*NP*DD    (1M)
//   k   : NB*HWT*DD   (4M)
//   v   : NB*HWT*DD   (4M)
//   att : NB*NP*DD    (1M)
// ---------------------------------------------------------------------------
#define LF_ELEMS  ((size_t)NB*NP*DD)
#define GF_ELEMS  ((size_t)NB*HWT*DD)
__device__ float g_scratch[LF_ELEMS + GF_ELEMS + LF_ELEMS + GF_ELEMS + GF_ELEMS + LF_ELEMS];

// ln(10000)
#define LN10K 9.210340371976184f

// ---------------------------------------------------------------------------
// Positional encodings (computed analytically, fused with the adds)
// pe[p, 2j]   = sin(x_p * exp(-2j*ln(1e4)/256))
// pe[p, 2j+1] = cos(y_p * exp(-2j*ln(1e4)/256))
// coords: p = yi*W + xi ; x = xi/(W-1), y = yi/(H-1)
// ---------------------------------------------------------------------------
__global__ void pe_local_kernel(const float* __restrict__ in, float* __restrict__ out) {
    int idx = blockIdx.x * blockDim.x + threadIdx.x;
    if (idx >= (int)LF_ELEMS) return;
    int d = idx & 255;
    int p = (idx >> 8) & (NP - 1);
    int j = d >> 1;
    float div = expf((float)(2 * j) * (-LN10K / 256.0f));
    float val;
    if ((d & 1) == 0) {
        float x = (float)(p & 31) * (1.0f / 31.0f);
        val = sinf(x * div);
    } else {
        float y = (float)(p >> 5) * (1.0f / 31.0f);
        val = cosf(y * div);
    }
    out[idx] = in[idx] + val;
}

// global_feat is (NB, DD, HWT); produce gf (NB, HWT, DD) with PE added
__global__ void pe_global_kernel(const float* __restrict__ in, float* __restrict__ out) {
    int idx = blockIdx.x * blockDim.x + threadIdx.x;
    if (idx >= (int)GF_ELEMS) return;
    int d = idx & 255;
    int t = (idx >> 8) & (HWT - 1);
    int b = idx >> 20;
    int j = d >> 1;
    float div = expf((float)(2 * j) * (-LN10K / 256.0f));
    float val;
    if ((d & 1) == 0) {
        float x = (float)(t & 63) * (1.0f / 63.0f);
        val = sinf(x * div);
    } else {
        float y = (float)(t >> 6) * (1.0f / 63.0f);
        val = cosf(y * div);
    }
    out[idx] = in[((size_t)b * DD + d) * HWT + t] + val;
}

// ---------------------------------------------------------------------------
// SGEMM: C[M,256] = (A (+A2)) [M,256] @ W[256,256]^T + bias
// 128x128 block tile, BK=8, 8x8 microtile, 256 threads.
// ---------------------------------------------------------------------------
template<bool FUSE>
__global__ __launch_bounds__(256) void sgemm_bias_kernel(
    const float* __restrict__ A, const float* __restrict__ A2,
    const float* __restrict__ W, const float* __restrict__ bias,
    float* __restrict__ C)
{
    const int K = 256;
    __shared__ float As[8][128];
    __shared__ float Bs[8][128];

    const int tid  = threadIdx.x;
    const int lrow = tid >> 1;          // 0..127
    const int lc4  = (tid & 1) << 2;    // 0 or 4
    const int mBase = blockIdx.y << 7;
    const int nBase = blockIdx.x << 7;

    const float* Ap  = A + (size_t)(mBase + lrow) * K + lc4;
    const float* A2p = FUSE ? (A2 + (size_t)(mBase + lrow) * K + lc4) : A;
    const float* Wp  = W + (size_t)(nBase + lrow) * K + lc4;

    const int ty = tid >> 4;   // 0..15
    const int tx = tid & 15;   // 0..15

    float acc[8][8];
    #pragma unroll
    for (int i = 0; i < 8; i++)
        #pragma unroll
        for (int jj = 0; jj < 8; jj++) acc[i][jj] = 0.0f;

    for (int k0 = 0; k0 < K; k0 += 8) {
        float4 a = *(const float4*)(Ap + k0);
        if (FUSE) {
            float4 a2 = *(const float4*)(A2p + k0);
            a.x += a2.x; a.y += a2.y; a.z += a2.z; a.w += a2.w;
        }
        float4 bb = *(const float4*)(Wp + k0);
        As[lc4 + 0][lrow] = a.x;  As[lc4 + 1][lrow] = a.y;
        As[lc4 + 2][lrow] = a.z;  As[lc4 + 3][lrow] = a.w;
        Bs[lc4 + 0][lrow] = bb.x; Bs[lc4 + 1][lrow] = bb.y;
        Bs[lc4 + 2][lrow] = bb.z; Bs[lc4 + 3][lrow] = bb.w;
        __syncthreads();

        #pragma unroll
        for (int kk = 0; kk < 8; kk++) {
            float ar[8], br[8];
            #pragma unroll
            for (int i = 0; i < 8; i++) ar[i] = As[kk][(ty << 3) + i];
            #pragma unroll
            for (int jj = 0; jj < 8; jj++) br[jj] = Bs[kk][(tx << 3) + jj];
            #pragma unroll
            for (int i = 0; i < 8; i++)
                #pragma unroll
                for (int jj = 0; jj < 8; jj++)
                    acc[i][jj] += ar[i] * br[jj];
        }
        __syncthreads();
    }

    const float4 b0 = *(const float4*)(bias + nBase + (tx << 3));
    const float4 b1 = *(const float4*)(bias + nBase + (tx << 3) + 4);
    #pragma unroll
    for (int i = 0; i < 8; i++) {
        int m = mBase + (ty << 3) + i;
        float4 r0 = make_float4(acc[i][0] + b0.x, acc[i][1] + b0.y,
                                acc[i][2] + b0.z, acc[i][3] + b0.w);
        float4 r1 = make_float4(acc[i][4] + b1.x, acc[i][5] + b1.y,
                                acc[i][6] + b1.z, acc[i][7] + b1.w);
        float* cp = C + (size_t)m * 256 + nBase + (tx << 3);
        *(float4*)(cp)     = r0;
        *(float4*)(cp + 4) = r1;
    }
}

// ---------------------------------------------------------------------------
// Flash attention, fp32. One thread per query row; grid (NP/128, HEADS, NB).
// K/V staged in smem (64 kv rows per chunk), online softmax in 16-wide subs.
// q layout: q[(b*NP+p)*DD + h*DH + d] ; k,v: [(b*HWT+t)*DD + h*DH + d]
// ---------------------------------------------------------------------------
__global__ __launch_bounds__(128) void flash_kernel(
    const float* __restrict__ q, const float* __restrict__ k,
    const float* __restrict__ v, float* __restrict__ out)
{
    const int tid = threadIdx.x;
    const int h = blockIdx.y;
    const int b = blockIdx.z;
    const int qi = (blockIdx.x << 7) + tid;

    __shared__ float4 Ks[64][8];
    __shared__ float4 Vs[64][8];

    float qr[32];
    {
        const float* qp = q + ((size_t)(b * NP + qi)) * DD + h * DH;
        #pragma unroll
        for (int c = 0; c < 8; c++) {
            float4 t4 = *(const float4*)(qp + c * 4);
            qr[4*c] = t4.x; qr[4*c+1] = t4.y; qr[4*c+2] = t4.z; qr[4*c+3] = t4.w;
        }
    }

    float o[32];
    #pragma unroll
    for (int i = 0; i < 32; i++) o[i] = 0.0f;
    float mM = -1e30f, l = 0.0f;
    const float scale = 0.17677669529663687f;  // 1/sqrt(32)

    for (int kv0 = 0; kv0 < HWT; kv0 += 64) {
        __syncthreads();
        #pragma unroll
        for (int it = 0; it < 4; it++) {
            int i = tid + it * 128;
            int r = i >> 3, c = i & 7;
            size_t off = ((size_t)(b * HWT + kv0 + r)) * DD + h * DH + c * 4;
            Ks[r][c] = *(const float4*)(k + off);
            Vs[r][c] = *(const float4*)(v + off);
        }
        __syncthreads();

        #pragma unroll
        for (int sub = 0; sub < 4; sub++) {
            float sc[16];
            #pragma unroll
            for (int j = 0; j < 16; j++) sc[j] = 0.0f;
            #pragma unroll
            for (int c = 0; c < 8; c++) {
                float qx = qr[4*c], qy = qr[4*c+1], qz = qr[4*c+2], qw = qr[4*c+3];
                #pragma unroll
                for (int j = 0; j < 16; j++) {
                    float4 k4 = Ks[sub * 16 + j][c];
                    sc[j] += qx * k4.x + qy * k4.y + qz * k4.z + qw * k4.w;
                }
            }
            float rowmax = -1e30f;
            #pragma unroll
            for (int j = 0; j < 16; j++) {
                sc[j] *= scale;
                rowmax = fmaxf(rowmax, sc[j]);
            }
            float mnew = fmaxf(mM, rowmax);
            float corr = __expf(mM - mnew);
            float psum = 0.0f;
            #pragma unroll
            for (int j = 0; j < 16; j++) {
                sc[j] = __expf(sc[j] - mnew);
                psum += sc[j];
            }
            l = l * corr + psum;
            mM = mnew;
            #pragma unroll
            for (int c = 0; c < 8; c++) {
                float ox = o[4*c] * corr, oy = o[4*c+1] * corr;
                float oz = o[4*c+2] * corr, ow = o[4*c+3] * corr;
                #pragma unroll
                for (int j = 0; j < 16; j++) {
                    float4 v4 = Vs[sub * 16 + j][c];
                    ox += sc[j] * v4.x; oy += sc[j] * v4.y;
                    oz += sc[j] * v4.z; ow += sc[j] * v4.w;
                }
                o[4*c] = ox; o[4*c+1] = oy; o[4*c+2] = oz; o[4*c+3] = ow;
            }
        }
    }

    float inv = 1.0f / l;
    float* op = out + ((size_t)(b * NP + qi)) * DD + h * DH;
    #pragma unroll
    for (int c = 0; c < 8; c++) {
        float4 r = make_float4(o[4*c] * inv, o[4*c+1] * inv,
                               o[4*c+2] * inv, o[4*c+3] * inv);
        *(float4*)(op + c * 4) = r;
    }
}

// ---------------------------------------------------------------------------
extern "C" void kernel_launch(void* const* d_in, const int* in_sizes, int n_in,
                              void* d_out, int out_size) {
    const float* local_feat  = (const float*)d_in[0];
    const float* global_feat = (const float*)d_in[1];
    const float* Wq = (const float*)d_in[2];
    const float* bq = (const float*)d_in[3];
    const float* Wk = (const float*)d_in[4];
    const float* bk = (const float*)d_in[5];
    const float* Wv = (const float*)d_in[6];
    const float* bv = (const float*)d_in[7];
    const float* Wo = (const float*)d_in[8];
    const float* bo = (const float*)d_in[9];
    float* out = (float*)d_out;

    float* base = nullptr;
    cudaGetSymbolAddress((void**)&base, g_scratch);
    float* lf  = base;
    float* gf  = lf + LF_ELEMS;
    float* q   = gf + GF_ELEMS;
    float* k   = q  + LF_ELEMS;
    float* v   = k  + GF_ELEMS;
    float* att = v  + GF_ELEMS;

    pe_local_kernel<<<(int)(LF_ELEMS / 256), 256>>>(local_feat, lf);
    pe_global_kernel<<<(int)(GF_ELEMS / 256), 256>>>(global_feat, gf);

    sgemm_bias_kernel<false><<<dim3(2, (NB * NP)  / 128), 256>>>(lf, nullptr, Wq, bq, q);
    sgemm_bias_kernel<false><<<dim3(2, (NB * HWT) / 128), 256>>>(gf, nullptr, Wk, bk, k);
    sgemm_bias_kernel<false><<<dim3(2, (NB * HWT) / 128), 256>>>(gf, nullptr, Wv, bv, v);

    flash_kernel<<<dim3(NP / 128, HEADS, NB), 128>>>(q, k, v, att);

    sgemm_bias_kernel<true><<<dim3(2, (NB * NP) / 128), 256>>>(lf, att, Wo, bo, out);
}

// round 4
// speedup vs baseline: 2.0866x; 2.0866x over previous
#include <cuda_runtime.h>
#include <cuda_fp16.h>
#include <stdint.h>
#include <stddef.h>
#include <math.h>

#define NB   4
#define NP   1024
#define DD   256
#define HH   64
#define WW   64
#define HWT  4096
#define HEADS 8
#define DH   32

#define LF_ELEMS  ((size_t)NB*NP*DD)
#define GF_ELEMS  ((size_t)NB*HWT*DD)
__device__ float g_scratch[LF_ELEMS + GF_ELEMS + LF_ELEMS + GF_ELEMS + GF_ELEMS + LF_ELEMS];

#define LN10K 9.210340371976184f

// ---------------------------------------------------------------------------
// Positional encodings (analytic, fused with the adds)
// ---------------------------------------------------------------------------
__global__ void pe_local_kernel(const float* __restrict__ in, float* __restrict__ out) {
    int idx = blockIdx.x * blockDim.x + threadIdx.x;
    if (idx >= (int)LF_ELEMS) return;
    int d = idx & 255;
    int p = (idx >> 8) & (NP - 1);
    int j = d >> 1;
    float div = expf((float)(2 * j) * (-LN10K / 256.0f));
    float val;
    if ((d & 1) == 0) {
        float x = (float)(p & 31) * (1.0f / 31.0f);
        val = sinf(x * div);
    } else {
        float y = (float)(p >> 5) * (1.0f / 31.0f);
        val = cosf(y * div);
    }
    out[idx] = in[idx] + val;
}

__global__ void pe_global_kernel(const float* __restrict__ in, float* __restrict__ out) {
    int idx = blockIdx.x * blockDim.x + threadIdx.x;
    if (idx >= (int)GF_ELEMS) return;
    int d = idx & 255;
    int t = (idx >> 8) & (HWT - 1);
    int b = idx >> 20;
    int j = d >> 1;
    float div = expf((float)(2 * j) * (-LN10K / 256.0f));
    float val;
    if ((d & 1) == 0) {
        float x = (float)(t & 63) * (1.0f / 63.0f);
        val = sinf(x * div);
    } else {
        float y = (float)(t >> 6) * (1.0f / 63.0f);
        val = cosf(y * div);
    }
    out[idx] = in[((size_t)b * DD + d) * HWT + t] + val;
}

// ---------------------------------------------------------------------------
// fp32 SGEMM for the projections
// ---------------------------------------------------------------------------
template<bool FUSE>
__global__ __launch_bounds__(256) void sgemm_bias_kernel(
    const float* __restrict__ A, const float* __restrict__ A2,
    const float* __restrict__ W, const float* __restrict__ bias,
    float* __restrict__ C)
{
    const int K = 256;
    __shared__ float As[8][128];
    __shared__ float Bs[8][128];

    const int tid  = threadIdx.x;
    const int lrow = tid >> 1;
    const int lc4  = (tid & 1) << 2;
    const int mBase = blockIdx.y << 7;
    const int nBase = blockIdx.x << 7;

    const float* Ap  = A + (size_t)(mBase + lrow) * K + lc4;
    const float* A2p = FUSE ? (A2 + (size_t)(mBase + lrow) * K + lc4) : A;
    const float* Wp  = W + (size_t)(nBase + lrow) * K + lc4;

    const int ty = tid >> 4;
    const int tx = tid & 15;

    float acc[8][8];
    #pragma unroll
    for (int i = 0; i < 8; i++)
        #pragma unroll
        for (int jj = 0; jj < 8; jj++) acc[i][jj] = 0.0f;

    for (int k0 = 0; k0 < K; k0 += 8) {
        float4 a = *(const float4*)(Ap + k0);
        if (FUSE) {
            float4 a2 = *(const float4*)(A2p + k0);
            a.x += a2.x; a.y += a2.y; a.z += a2.z; a.w += a2.w;
        }
        float4 bb = *(const float4*)(Wp + k0);
        As[lc4 + 0][lrow] = a.x;  As[lc4 + 1][lrow] = a.y;
        As[lc4 + 2][lrow] = a.z;  As[lc4 + 3][lrow] = a.w;
        Bs[lc4 + 0][lrow] = bb.x; Bs[lc4 + 1][lrow] = bb.y;
        Bs[lc4 + 2][lrow] = bb.z; Bs[lc4 + 3][lrow] = bb.w;
        __syncthreads();

        #pragma unroll
        for (int kk = 0; kk < 8; kk++) {
            float ar[8], br[8];
            #pragma unroll
            for (int i = 0; i < 8; i++) ar[i] = As[kk][(ty << 3) + i];
            #pragma unroll
            for (int jj = 0; jj < 8; jj++) br[jj] = Bs[kk][(tx << 3) + jj];
            #pragma unroll
            for (int i = 0; i < 8; i++)
                #pragma unroll
                for (int jj = 0; jj < 8; jj++)
                    acc[i][jj] += ar[i] * br[jj];
        }
        __syncthreads();
    }

    const float4 b0 = *(const float4*)(bias + nBase + (tx << 3));
    const float4 b1 = *(const float4*)(bias + nBase + (tx << 3) + 4);
    #pragma unroll
    for (int i = 0; i < 8; i++) {
        int m = mBase + (ty << 3) + i;
        float4 r0 = make_float4(acc[i][0] + b0.x, acc[i][1] + b0.y,
                                acc[i][2] + b0.z, acc[i][3] + b0.w);
        float4 r1 = make_float4(acc[i][4] + b1.x, acc[i][5] + b1.y,
                                acc[i][6] + b1.z, acc[i][7] + b1.w);
        float* cp = C + (size_t)m * 256 + nBase + (tx << 3);
        *(float4*)(cp)     = r0;
        *(float4*)(cp + 4) = r1;
    }
}

// ---------------------------------------------------------------------------
// Tensor-core flash attention.
// Block = 64 queries (4 warps x 16 rows), KV tile = 64 keys, cp.async double
// buffered. QK^T: mma.m16n8k8 tf32. PV: mma.m16n8k16 f16 (P in [0,1]).
// fp32 accumulate + fp32 online softmax.
// ---------------------------------------------------------------------------
__device__ __forceinline__ void cp16(uint32_t dst, const void* src) {
    asm volatile("cp.async.cg.shared.global [%0], [%1], 16;\n" :: "r"(dst), "l"(src));
}

__device__ __forceinline__ void mma_tf32(float& c0, float& c1, float& c2, float& c3,
                                         const uint32_t a[4], uint32_t b0, uint32_t b1) {
    asm volatile(
        "mma.sync.aligned.m16n8k8.row.col.f32.tf32.tf32.f32 "
        "{%0,%1,%2,%3}, {%4,%5,%6,%7}, {%8,%9}, {%0,%1,%2,%3};\n"
        : "+f"(c0), "+f"(c1), "+f"(c2), "+f"(c3)
        : "r"(a[0]), "r"(a[1]), "r"(a[2]), "r"(a[3]), "r"(b0), "r"(b1));
}

__device__ __forceinline__ void mma_f16(float& c0, float& c1, float& c2, float& c3,
                                        uint32_t a0, uint32_t a1, uint32_t a2, uint32_t a3,
                                        uint32_t b0, uint32_t b1) {
    asm volatile(
        "mma.sync.aligned.m16n8k16.row.col.f32.f16.f16.f32 "
        "{%0,%1,%2,%3}, {%4,%5,%6,%7}, {%8,%9}, {%0,%1,%2,%3};\n"
        : "+f"(c0), "+f"(c1), "+f"(c2), "+f"(c3)
        : "r"(a0), "r"(a1), "r"(a2), "r"(a3), "r"(b0), "r"(b1));
}

__device__ __forceinline__ uint32_t pack_h2(float lo, float hi) {
    __half2 h = __floats2half2_rn(lo, hi);
    return *reinterpret_cast<uint32_t*>(&h);
}

#define KPAD 36

__global__ __launch_bounds__(128, 4) void flash_mma_kernel(
    const float* __restrict__ q, const float* __restrict__ k,
    const float* __restrict__ v, float* __restrict__ out)
{
    __shared__ float Ks[2][64][KPAD];
    __shared__ float Vs[2][64][KPAD];

    const int tid  = threadIdx.x;
    const int warp = tid >> 5;
    const int lane = tid & 31;
    const int gi = lane >> 2;   // row-group within fragment (0..7)
    const int ci = lane & 3;    // thread-in-group (0..3)
    const int b = blockIdx.z;
    const int h = blockIdx.y;
    const int qbase = (blockIdx.x << 6) + warp * 16;

    // Load + scale Q fragments (tf32). a0:(gi, c) a1:(gi+8, c) a2:(gi, c+4) a3:(gi+8, c+4)
    uint32_t qf[4][4];
    {
        const float scale = 0.17677669529663687f;  // 1/sqrt(32)
        const float* qp = q + ((size_t)(b * NP + qbase)) * DD + h * DH;
        #pragma unroll
        for (int s = 0; s < 4; s++) {
            float a0 = qp[(size_t)gi * DD       + s * 8 + ci    ] * scale;
            float a1 = qp[(size_t)(gi + 8) * DD + s * 8 + ci    ] * scale;
            float a2 = qp[(size_t)gi * DD       + s * 8 + ci + 4] * scale;
            float a3 = qp[(size_t)(gi + 8) * DD + s * 8 + ci + 4] * scale;
            asm("cvt.rna.tf32.f32 %0, %1;" : "=r"(qf[s][0]) : "f"(a0));
            asm("cvt.rna.tf32.f32 %0, %1;" : "=r"(qf[s][1]) : "f"(a1));
            asm("cvt.rna.tf32.f32 %0, %1;" : "=r"(qf[s][2]) : "f"(a2));
            asm("cvt.rna.tf32.f32 %0, %1;" : "=r"(qf[s][3]) : "f"(a3));
        }
    }

    float O[4][4];
    #pragma unroll
    for (int n = 0; n < 4; n++)
        #pragma unroll
        for (int i = 0; i < 4; i++) O[n][i] = 0.0f;
    float m0 = -1e30f, m1 = -1e30f, l0 = 0.0f, l1 = 0.0f;

    const float* kbase = k + ((size_t)b * HWT) * DD + h * DH;
    const float* vbase = v + ((size_t)b * HWT) * DD + h * DH;

    // Issue tile 0: each thread covers 4 K chunks + 4 V chunks of 16B
    {
        #pragma unroll
        for (int j = 0; j < 4; j++) {
            int idx = tid * 4 + j;             // 0..511
            int key = idx >> 3, ch = idx & 7;
            uint32_t dk = (uint32_t)__cvta_generic_to_shared(&Ks[0][key][ch * 4]);
            uint32_t dv = (uint32_t)__cvta_generic_to_shared(&Vs[0][key][ch * 4]);
            cp16(dk, kbase + (size_t)key * DD + ch * 4);
            cp16(dv, vbase + (size_t)key * DD + ch * 4);
        }
        asm volatile("cp.async.commit_group;\n");
    }

    for (int t = 0; t < 64; t++) {
        const int buf = t & 1;
        if (t < 63) {
            const int nb_ = (t + 1) & 1;
            const size_t kv0 = (size_t)(t + 1) << 6;
            #pragma unroll
            for (int j = 0; j < 4; j++) {
                int idx = tid * 4 + j;
                int key = idx >> 3, ch = idx & 7;
                uint32_t dk = (uint32_t)__cvta_generic_to_shared(&Ks[nb_][key][ch * 4]);
                uint32_t dv = (uint32_t)__cvta_generic_to_shared(&Vs[nb_][key][ch * 4]);
                cp16(dk, kbase + (kv0 + key) * DD + ch * 4);
                cp16(dv, vbase + (kv0 + key) * DD + ch * 4);
            }
            asm volatile("cp.async.commit_group;\n");
            asm volatile("cp.async.wait_group 1;\n");
        } else {
            asm volatile("cp.async.wait_group 0;\n");
        }
        __syncthreads();

        // ---- S = Q K^T (tf32 mma), 8 n-tiles of 8 keys ----
        float Sf[8][4];
        #pragma unroll
        for (int nt = 0; nt < 8; nt++) {
            float c0 = 0.f, c1 = 0.f, c2 = 0.f, c3 = 0.f;
            #pragma unroll
            for (int s = 0; s < 4; s++) {
                uint32_t b0 = __float_as_uint(Ks[buf][nt * 8 + gi][s * 8 + ci]);
                uint32_t b1 = __float_as_uint(Ks[buf][nt * 8 + gi][s * 8 + ci + 4]);
                mma_tf32(c0, c1, c2, c3, qf[s], b0, b1);
            }
            Sf[nt][0] = c0; Sf[nt][1] = c1; Sf[nt][2] = c2; Sf[nt][3] = c3;
        }

        // ---- online softmax ----
        float mx0 = -1e30f, mx1 = -1e30f;
        #pragma unroll
        for (int nt = 0; nt < 8; nt++) {
            mx0 = fmaxf(mx0, fmaxf(Sf[nt][0], Sf[nt][1]));
            mx1 = fmaxf(mx1, fmaxf(Sf[nt][2], Sf[nt][3]));
        }
        mx0 = fmaxf(mx0, __shfl_xor_sync(0xffffffffu, mx0, 1));
        mx0 = fmaxf(mx0, __shfl_xor_sync(0xffffffffu, mx0, 2));
        mx1 = fmaxf(mx1, __shfl_xor_sync(0xffffffffu, mx1, 1));
        mx1 = fmaxf(mx1, __shfl_xor_sync(0xffffffffu, mx1, 2));

        float mn0 = fmaxf(m0, mx0), mn1 = fmaxf(m1, mx1);
        float corr0 = __expf(m0 - mn0), corr1 = __expf(m1 - mn1);
        float sum0 = 0.f, sum1 = 0.f;
        #pragma unroll
        for (int nt = 0; nt < 8; nt++) {
            Sf[nt][0] = __expf(Sf[nt][0] - mn0); sum0 += Sf[nt][0];
            Sf[nt][1] = __expf(Sf[nt][1] - mn0); sum0 += Sf[nt][1];
            Sf[nt][2] = __expf(Sf[nt][2] - mn1); sum1 += Sf[nt][2];
            Sf[nt][3] = __expf(Sf[nt][3] - mn1); sum1 += Sf[nt][3];
        }
        sum0 += __shfl_xor_sync(0xffffffffu, sum0, 1);
        sum0 += __shfl_xor_sync(0xffffffffu, sum0, 2);
        sum1 += __shfl_xor_sync(0xffffffffu, sum1, 1);
        sum1 += __shfl_xor_sync(0xffffffffu, sum1, 2);
        l0 = l0 * corr0 + sum0;
        l1 = l1 * corr1 + sum1;
        m0 = mn0; m1 = mn1;

        #pragma unroll
        for (int n = 0; n < 4; n++) {
            O[n][0] *= corr0; O[n][1] *= corr0;
            O[n][2] *= corr1; O[n][3] *= corr1;
        }

        // ---- O += P V (f16 mma): 4 k-steps of 16 keys, 4 dh-tiles of 8 ----
        #pragma unroll
        for (int s = 0; s < 4; s++) {
            uint32_t a0 = pack_h2(Sf[2 * s][0],     Sf[2 * s][1]);
            uint32_t a1 = pack_h2(Sf[2 * s][2],     Sf[2 * s][3]);
            uint32_t a2 = pack_h2(Sf[2 * s + 1][0], Sf[2 * s + 1][1]);
            uint32_t a3 = pack_h2(Sf[2 * s + 1][2], Sf[2 * s + 1][3]);
            int key0 = s * 16 + 2 * ci;
            #pragma unroll
            for (int n = 0; n < 4; n++) {
                int col = n * 8 + gi;
                uint32_t b0 = pack_h2(Vs[buf][key0][col],     Vs[buf][key0 + 1][col]);
                uint32_t b1 = pack_h2(Vs[buf][key0 + 8][col], Vs[buf][key0 + 9][col]);
                mma_f16(O[n][0], O[n][1], O[n][2], O[n][3], a0, a1, a2, a3, b0, b1);
            }
        }
        __syncthreads();
    }

    // ---- epilogue ----
    float inv0 = 1.0f / l0, inv1 = 1.0f / l1;
    float* op = out + ((size_t)(b * NP + qbase)) * DD + h * DH;
    #pragma unroll
    for (int n = 0; n < 4; n++) {
        float2 r0 = make_float2(O[n][0] * inv0, O[n][1] * inv0);
        float2 r1 = make_float2(O[n][2] * inv1, O[n][3] * inv1);
        *(float2*)(op + (size_t)gi * DD       + n * 8 + 2 * ci) = r0;
        *(float2*)(op + (size_t)(gi + 8) * DD + n * 8 + 2 * ci) = r1;
    }
}

// ---------------------------------------------------------------------------
extern "C" void kernel_launch(void* const* d_in, const int* in_sizes, int n_in,
                              void* d_out, int out_size) {
    const float* local_feat  = (const float*)d_in[0];
    const float* global_feat = (const float*)d_in[1];
    const float* Wq = (const float*)d_in[2];
    const float* bq = (const float*)d_in[3];
    const float* Wk = (const float*)d_in[4];
    const float* bk = (const float*)d_in[5];
    const float* Wv = (const float*)d_in[6];
    const float* bv = (const float*)d_in[7];
    const float* Wo = (const float*)d_in[8];
    const float* bo = (const float*)d_in[9];
    float* out = (float*)d_out;

    float* base = nullptr;
    cudaGetSymbolAddress((void**)&base, g_scratch);
    float* lf  = base;
    float* gf  = lf + LF_ELEMS;
    float* q   = gf + GF_ELEMS;
    float* k   = q  + LF_ELEMS;
    float* v   = k  + GF_ELEMS;
    float* att = v  + GF_ELEMS;

    pe_local_kernel<<<(int)(LF_ELEMS / 256), 256>>>(local_feat, lf);
    pe_global_kernel<<<(int)(GF_ELEMS / 256), 256>>>(global_feat, gf);

    sgemm_bias_kernel<false><<<dim3(2, (NB * NP)  / 128), 256>>>(lf, nullptr, Wq, bq, q);
    sgemm_bias_kernel<false><<<dim3(2, (NB * HWT) / 128), 256>>>(gf, nullptr, Wk, bk, k);
    sgemm_bias_kernel<false><<<dim3(2, (NB * HWT) / 128), 256>>>(gf, nullptr, Wv, bv, v);

    flash_mma_kernel<<<dim3(NP / 64, HEADS, NB), 128>>>(q, k, v, att);

    sgemm_bias_kernel<true><<<dim3(2, (NB * NP) / 128), 256>>>(lf, att, Wo, bo, out);
}

// round 5
// speedup vs baseline: 3.0201x; 1.4474x over previous
#include <cuda_runtime.h>
#include <cuda_fp16.h>
#include <stdint.h>
#include <stddef.h>
#include <math.h>

#define NB   4
#define NP   1024
#define DD   256
#define HWT  4096
#define HEADS 8
#define DH   32

#define LF_ELEMS  ((size_t)NB*NP*DD)
#define GF_ELEMS  ((size_t)NB*HWT*DD)
// lf, gf, q, k, v, att, tmp
__device__ float g_scratch[LF_ELEMS + GF_ELEMS + LF_ELEMS + GF_ELEMS + GF_ELEMS + LF_ELEMS + LF_ELEMS];

#define LN10K 9.210340371976184f

// ---------------------------------------------------------------------------
// PTX helpers
// ---------------------------------------------------------------------------
__device__ __forceinline__ void cp16(uint32_t dst, const void* src) {
    asm volatile("cp.async.cg.shared.global [%0], [%1], 16;\n" :: "r"(dst), "l"(src));
}
__device__ __forceinline__ uint32_t smem_u32(const void* p) {
    return (uint32_t)__cvta_generic_to_shared(p);
}
__device__ __forceinline__ void mma_tf32(float& c0, float& c1, float& c2, float& c3,
                                         const uint32_t a[4], uint32_t b0, uint32_t b1) {
    asm volatile(
        "mma.sync.aligned.m16n8k8.row.col.f32.tf32.tf32.f32 "
        "{%0,%1,%2,%3}, {%4,%5,%6,%7}, {%8,%9}, {%0,%1,%2,%3};\n"
        : "+f"(c0), "+f"(c1), "+f"(c2), "+f"(c3)
        : "r"(a[0]), "r"(a[1]), "r"(a[2]), "r"(a[3]), "r"(b0), "r"(b1));
}
__device__ __forceinline__ void mma_f16(float& c0, float& c1, float& c2, float& c3,
                                        uint32_t a0, uint32_t a1, uint32_t a2, uint32_t a3,
                                        uint32_t b0, uint32_t b1) {
    asm volatile(
        "mma.sync.aligned.m16n8k16.row.col.f32.f16.f16.f32 "
        "{%0,%1,%2,%3}, {%4,%5,%6,%7}, {%8,%9}, {%0,%1,%2,%3};\n"
        : "+f"(c0), "+f"(c1), "+f"(c2), "+f"(c3)
        : "r"(a0), "r"(a1), "r"(a2), "r"(a3), "r"(b0), "r"(b1));
}
__device__ __forceinline__ uint32_t pack_h2(float lo, float hi) {
    __half2 h = __floats2half2_rn(lo, hi);
    return *reinterpret_cast<uint32_t*>(&h);
}
__device__ __forceinline__ uint32_t to_tf32(float x) {
    uint32_t r;
    asm("cvt.rna.tf32.f32 %0, %1;" : "=r"(r) : "f"(x));
    return r;
}

// ---------------------------------------------------------------------------
// Positional encodings
// ---------------------------------------------------------------------------
__global__ void pe_local_kernel(const float* __restrict__ in, float* __restrict__ out) {
    int idx = blockIdx.x * blockDim.x + threadIdx.x;
    if (idx >= (int)LF_ELEMS) return;
    int d = idx & 255;
    int p = (idx >> 8) & (NP - 1);
    float div = expf((float)(d & ~1) * (-LN10K / 256.0f));
    float val;
    if ((d & 1) == 0) {
        float x = (float)(p & 31) * (1.0f / 31.0f);
        val = sinf(x * div);
    } else {
        float y = (float)(p >> 5) * (1.0f / 31.0f);
        val = cosf(y * div);
    }
    out[idx] = in[idx] + val;
}

// global_feat (NB, DD, HWT) -> gf (NB, HWT, DD) + PE, via 32x32 smem transpose
__global__ __launch_bounds__(256) void pe_global_kernel(const float* __restrict__ in,
                                                        float* __restrict__ out) {
    __shared__ float tile[32][33];
    const int tx = threadIdx.x & 31;
    const int ty = threadIdx.x >> 5;     // 0..7
    const int t0 = blockIdx.x << 5;
    const int d0 = blockIdx.y << 5;
    const int b  = blockIdx.z;

    #pragma unroll
    for (int i = 0; i < 4; i++) {
        int d = d0 + ty + i * 8;
        tile[ty + i * 8][tx] = in[((size_t)b * DD + d) * HWT + t0 + tx];
    }
    __syncthreads();
    #pragma unroll
    for (int i = 0; i < 4; i++) {
        int t = t0 + ty + i * 8;
        int d = d0 + tx;
        float div = expf((float)(d & ~1) * (-LN10K / 256.0f));
        float val;
        if ((d & 1) == 0) {
            float x = (float)(t & 63) * (1.0f / 63.0f);
            val = sinf(x * div);
        } else {
            float y = (float)(t >> 6) * (1.0f / 63.0f);
            val = cosf(y * div);
        }
        out[((size_t)b * HWT + t) * DD + d] = tile[tx][ty + i * 8] + val;
    }
}

__global__ void add_kernel(const float* __restrict__ a, const float* __restrict__ b,
                           float* __restrict__ out) {
    int idx = blockIdx.x * blockDim.x + threadIdx.x;
    float4 x = ((const float4*)a)[idx];
    float4 y = ((const float4*)b)[idx];
    x.x += y.x; x.y += y.y; x.z += y.z; x.w += y.w;
    ((float4*)out)[idx] = x;
}

// ---------------------------------------------------------------------------
// tf32 tensor-core GEMM: C[M,256] = A[M,256] @ W^T + bias
// 128x128 tile, 8 warps, BK=16 double-buffered cp.async.
// Warp tile 32x64: 2 m-tiles x 8 n-tiles of m16n8k8.
// ---------------------------------------------------------------------------
__global__ __launch_bounds__(256) void gemm_tf32_kernel(
    const float* __restrict__ A, const float* __restrict__ W,
    const float* __restrict__ bias, float* __restrict__ C)
{
    __shared__ float As[2][128][20];
    __shared__ float Ws[2][128][20];

    const int tid  = threadIdx.x;
    const int warp = tid >> 5;
    const int lane = tid & 31;
    const int gi = lane >> 2;
    const int ci = lane & 3;
    const int mBase = blockIdx.y << 7;
    const int nBase = blockIdx.x << 7;
    const int wm = (warp & 3) << 5;   // 0,32,64,96
    const int wn = (warp >> 2) << 6;  // 0,64

    float acc[2][8][4];
    #pragma unroll
    for (int mt = 0; mt < 2; mt++)
        #pragma unroll
        for (int nt = 0; nt < 8; nt++)
            #pragma unroll
            for (int i = 0; i < 4; i++) acc[mt][nt][i] = 0.0f;

    // prefetch k-tile 0
    {
        #pragma unroll
        for (int j = 0; j < 2; j++) {
            int idx = tid * 2 + j;            // 0..511
            int r = idx >> 2, c = (idx & 3) * 4;
            cp16(smem_u32(&As[0][r][c]), A + (size_t)(mBase + r) * 256 + c);
            cp16(smem_u32(&Ws[0][r][c]), W + (size_t)(nBase + r) * 256 + c);
        }
        asm volatile("cp.async.commit_group;\n");
    }

    for (int kt = 0; kt < 16; kt++) {
        const int buf = kt & 1;
        if (kt < 15) {
            const int nb_ = buf ^ 1;
            const int k0 = (kt + 1) * 16;
            #pragma unroll
            for (int j = 0; j < 2; j++) {
                int idx = tid * 2 + j;
                int r = idx >> 2, c = (idx & 3) * 4;
                cp16(smem_u32(&As[nb_][r][c]), A + (size_t)(mBase + r) * 256 + k0 + c);
                cp16(smem_u32(&Ws[nb_][r][c]), W + (size_t)(nBase + r) * 256 + k0 + c);
            }
            asm volatile("cp.async.commit_group;\n");
            asm volatile("cp.async.wait_group 1;\n");
        } else {
            asm volatile("cp.async.wait_group 0;\n");
        }
        __syncthreads();

        #pragma unroll
        for (int ks = 0; ks < 2; ks++) {
            uint32_t af[2][4];
            #pragma unroll
            for (int mt = 0; mt < 2; mt++) {
                af[mt][0] = to_tf32(As[buf][wm + mt * 16 + gi    ][ks * 8 + ci    ]);
                af[mt][1] = to_tf32(As[buf][wm + mt * 16 + gi + 8][ks * 8 + ci    ]);
                af[mt][2] = to_tf32(As[buf][wm + mt * 16 + gi    ][ks * 8 + ci + 4]);
                af[mt][3] = to_tf32(As[buf][wm + mt * 16 + gi + 8][ks * 8 + ci + 4]);
            }
            #pragma unroll
            for (int nt = 0; nt < 8; nt++) {
                uint32_t b0 = __float_as_uint(Ws[buf][wn + nt * 8 + gi][ks * 8 + ci    ]);
                uint32_t b1 = __float_as_uint(Ws[buf][wn + nt * 8 + gi][ks * 8 + ci + 4]);
                #pragma unroll
                for (int mt = 0; mt < 2; mt++)
                    mma_tf32(acc[mt][nt][0], acc[mt][nt][1], acc[mt][nt][2], acc[mt][nt][3],
                             af[mt], b0, b1);
            }
        }
        __syncthreads();
    }

    #pragma unroll
    for (int mt = 0; mt < 2; mt++) {
        #pragma unroll
        for (int nt = 0; nt < 8; nt++) {
            int ncol = nBase + wn + nt * 8 + 2 * ci;
            float2 bs = *(const float2*)(bias + ncol);
            int r0 = mBase + wm + mt * 16 + gi;
            float2 o0 = make_float2(acc[mt][nt][0] + bs.x, acc[mt][nt][1] + bs.y);
            float2 o1 = make_float2(acc[mt][nt][2] + bs.x, acc[mt][nt][3] + bs.y);
            *(float2*)(C + (size_t)r0 * 256 + ncol)       = o0;
            *(float2*)(C + (size_t)(r0 + 8) * 256 + ncol) = o1;
        }
    }
}

// ---------------------------------------------------------------------------
// Flash attention: 64 queries/block (4 warps x 16), KV tile 64, double buffer.
// QK^T tf32 mma; V converted once/tile to transposed half2; PV f16 mma.
// ---------------------------------------------------------------------------
#define KPAD 36

__global__ __launch_bounds__(128, 4) void flash_mma_kernel(
    const float* __restrict__ q, const float* __restrict__ k,
    const float* __restrict__ v, float* __restrict__ out)
{
    __shared__ float    Ks[2][64][KPAD];
    __shared__ float    Vs[2][64][KPAD];
    __shared__ uint32_t Vh[2][32][KPAD];   // [dh][key/2] as half2

    const int tid  = threadIdx.x;
    const int warp = tid >> 5;
    const int lane = tid & 31;
    const int gi = lane >> 2;
    const int ci = lane & 3;
    const int b = blockIdx.z;
    const int h = blockIdx.y;
    const int qbase = (blockIdx.x << 6) + warp * 16;

    uint32_t qf[4][4];
    {
        const float scale = 0.17677669529663687f;  // 1/sqrt(32)
        const float* qp = q + ((size_t)(b * NP + qbase)) * DD + h * DH;
        #pragma unroll
        for (int s = 0; s < 4; s++) {
            qf[s][0] = to_tf32(qp[(size_t)gi * DD       + s * 8 + ci    ] * scale);
            qf[s][1] = to_tf32(qp[(size_t)(gi + 8) * DD + s * 8 + ci    ] * scale);
            qf[s][2] = to_tf32(qp[(size_t)gi * DD       + s * 8 + ci + 4] * scale);
            qf[s][3] = to_tf32(qp[(size_t)(gi + 8) * DD + s * 8 + ci + 4] * scale);
        }
    }

    float O[4][4];
    #pragma unroll
    for (int n = 0; n < 4; n++)
        #pragma unroll
        for (int i = 0; i < 4; i++) O[n][i] = 0.0f;
    float m0 = -1e30f, m1 = -1e30f, l0 = 0.0f, l1 = 0.0f;

    const float* kbase = k + ((size_t)b * HWT) * DD + h * DH;
    const float* vbase = v + ((size_t)b * HWT) * DD + h * DH;

    {
        #pragma unroll
        for (int j = 0; j < 4; j++) {
            int idx = tid * 4 + j;             // 0..511
            int key = idx >> 3, ch = idx & 7;
            cp16(smem_u32(&Ks[0][key][ch * 4]), kbase + (size_t)key * DD + ch * 4);
            cp16(smem_u32(&Vs[0][key][ch * 4]), vbase + (size_t)key * DD + ch * 4);
        }
        asm volatile("cp.async.commit_group;\n");
    }

    for (int t = 0; t < 64; t++) {
        const int buf = t & 1;
        if (t < 63) {
            const int nb_ = buf ^ 1;
            const size_t kv0 = (size_t)(t + 1) << 6;
            #pragma unroll
            for (int j = 0; j < 4; j++) {
                int idx = tid * 4 + j;
                int key = idx >> 3, ch = idx & 7;
                cp16(smem_u32(&Ks[nb_][key][ch * 4]), kbase + (kv0 + key) * DD + ch * 4);
                cp16(smem_u32(&Vs[nb_][key][ch * 4]), vbase + (kv0 + key) * DD + ch * 4);
            }
            asm volatile("cp.async.commit_group;\n");
            asm volatile("cp.async.wait_group 1;\n");
        } else {
            asm volatile("cp.async.wait_group 0;\n");
        }
        __syncthreads();   // S1: tile visible

        // cooperative V -> transposed half2 (each thread: col=lane, k2=warp*8+j)
        #pragma unroll
        for (int j = 0; j < 8; j++) {
            int k2 = warp * 8 + j;
            Vh[buf][lane][k2] = pack_h2(Vs[buf][2 * k2][lane], Vs[buf][2 * k2 + 1][lane]);
        }

        // ---- S = Q K^T ----
        float Sf[8][4];
        #pragma unroll
        for (int nt = 0; nt < 8; nt++) {
            float c0 = 0.f, c1 = 0.f, c2 = 0.f, c3 = 0.f;
            #pragma unroll
            for (int s = 0; s < 4; s++) {
                uint32_t b0 = __float_as_uint(Ks[buf][nt * 8 + gi][s * 8 + ci]);
                uint32_t b1 = __float_as_uint(Ks[buf][nt * 8 + gi][s * 8 + ci + 4]);
                mma_tf32(c0, c1, c2, c3, qf[s], b0, b1);
            }
            Sf[nt][0] = c0; Sf[nt][1] = c1; Sf[nt][2] = c2; Sf[nt][3] = c3;
        }

        // ---- online softmax ----
        float mx0 = -1e30f, mx1 = -1e30f;
        #pragma unroll
        for (int nt = 0; nt < 8; nt++) {
            mx0 = fmaxf(mx0, fmaxf(Sf[nt][0], Sf[nt][1]));
            mx1 = fmaxf(mx1, fmaxf(Sf[nt][2], Sf[nt][3]));
        }
        mx0 = fmaxf(mx0, __shfl_xor_sync(0xffffffffu, mx0, 1));
        mx0 = fmaxf(mx0, __shfl_xor_sync(0xffffffffu, mx0, 2));
        mx1 = fmaxf(mx1, __shfl_xor_sync(0xffffffffu, mx1, 1));
        mx1 = fmaxf(mx1, __shfl_xor_sync(0xffffffffu, mx1, 2));

        float mn0 = fmaxf(m0, mx0), mn1 = fmaxf(m1, mx1);
        float corr0 = __expf(m0 - mn0), corr1 = __expf(m1 - mn1);
        float sum0 = 0.f, sum1 = 0.f;
        #pragma unroll
        for (int nt = 0; nt < 8; nt++) {
            Sf[nt][0] = __expf(Sf[nt][0] - mn0); sum0 += Sf[nt][0];
            Sf[nt][1] = __expf(Sf[nt][1] - mn0); sum0 += Sf[nt][1];
            Sf[nt][2] = __expf(Sf[nt][2] - mn1); sum1 += Sf[nt][2];
            Sf[nt][3] = __expf(Sf[nt][3] - mn1); sum1 += Sf[nt][3];
        }
        sum0 += __shfl_xor_sync(0xffffffffu, sum0, 1);
        sum0 += __shfl_xor_sync(0xffffffffu, sum0, 2);
        sum1 += __shfl_xor_sync(0xffffffffu, sum1, 1);
        sum1 += __shfl_xor_sync(0xffffffffu, sum1, 2);
        l0 = l0 * corr0 + sum0;
        l1 = l1 * corr1 + sum1;
        m0 = mn0; m1 = mn1;

        #pragma unroll
        for (int n = 0; n < 4; n++) {
            O[n][0] *= corr0; O[n][1] *= corr0;
            O[n][2] *= corr1; O[n][3] *= corr1;
        }

        __syncthreads();   // S2: all converts visible; Ks reads done

        // ---- O += P V ----
        #pragma unroll
        for (int s = 0; s < 4; s++) {
            uint32_t a0 = pack_h2(Sf[2 * s][0],     Sf[2 * s][1]);
            uint32_t a1 = pack_h2(Sf[2 * s][2],     Sf[2 * s][3]);
            uint32_t a2 = pack_h2(Sf[2 * s + 1][0], Sf[2 * s + 1][1]);
            uint32_t a3 = pack_h2(Sf[2 * s + 1][2], Sf[2 * s + 1][3]);
            #pragma unroll
            for (int n = 0; n < 4; n++) {
                int col = n * 8 + gi;
                uint32_t b0 = Vh[buf][col][s * 8 + ci];
                uint32_t b1 = Vh[buf][col][s * 8 + ci + 4];
                mma_f16(O[n][0], O[n][1], O[n][2], O[n][3], a0, a1, a2, a3, b0, b1);
            }
        }
    }

    float inv0 = 1.0f / l0, inv1 = 1.0f / l1;
    float* op = out + ((size_t)(b * NP + qbase)) * DD + h * DH;
    #pragma unroll
    for (int n = 0; n < 4; n++) {
        float2 r0 = make_float2(O[n][0] * inv0, O[n][1] * inv0);
        float2 r1 = make_float2(O[n][2] * inv1, O[n][3] * inv1);
        *(float2*)(op + (size_t)gi * DD       + n * 8 + 2 * ci) = r0;
        *(float2*)(op + (size_t)(gi + 8) * DD + n * 8 + 2 * ci) = r1;
    }
}

// ---------------------------------------------------------------------------
extern "C" void kernel_launch(void* const* d_in, const int* in_sizes, int n_in,
                              void* d_out, int out_size) {
    const float* local_feat  = (const float*)d_in[0];
    const float* global_feat = (const float*)d_in[1];
    const float* Wq = (const float*)d_in[2];
    const float* bq = (const float*)d_in[3];
    const float* Wk = (const float*)d_in[4];
    const float* bk = (const float*)d_in[5];
    const float* Wv = (const float*)d_in[6];
    const float* bv = (const float*)d_in[7];
    const float* Wo = (const float*)d_in[8];
    const float* bo = (const float*)d_in[9];
    float* out = (float*)d_out;

    float* base = nullptr;
    cudaGetSymbolAddress((void**)&base, g_scratch);
    float* lf  = base;
    float* gf  = lf  + LF_ELEMS;
    float* q   = gf  + GF_ELEMS;
    float* k   = q   + LF_ELEMS;
    float* v   = k   + GF_ELEMS;
    float* att = v   + GF_ELEMS;
    float* tmp = att + LF_ELEMS;

    pe_local_kernel<<<(int)(LF_ELEMS / 256), 256>>>(local_feat, lf);
    pe_global_kernel<<<dim3(HWT / 32, DD / 32, NB), 256>>>(global_feat, gf);

    gemm_tf32_kernel<<<dim3(2, (NB * NP)  / 128), 256>>>(lf, Wq, bq, q);
    gemm_tf32_kernel<<<dim3(2, (NB * HWT) / 128), 256>>>(gf, Wk, bk, k);
    gemm_tf32_kernel<<<dim3(2, (NB * HWT) / 128), 256>>>(gf, Wv, bv, v);

    flash_mma_kernel<<<dim3(NP / 64, HEADS, NB), 128>>>(q, k, v, att);

    add_kernel<<<(int)(LF_ELEMS / 1024), 256>>>(lf, att, tmp);
    gemm_tf32_kernel<<<dim3(2, (NB * NP) / 128), 256>>>(tmp, Wo, bo, out);
}